// round 14
// baseline (speedup 1.0000x reference)
#include <cuda_runtime.h>
#include <cstdint>

#define BATCH 8192
#define DDIM  1024
#define KDIM  2048
#define EDIM  512
#define BETA  0.001
#define BETAF 0.001f

#define NBLK 512   // 256 thr, <=64 regs (launch_bounds) -> 4 blocks/SM * 148 SMs = 592 resident

// ---------------- scratch (static device arrays; no cudaMalloc) ----------------
__device__ float g_R  [EDIM];   // R_e = sum_k rw[e,k]            (phase A, no atomics)
__device__ float g_Q  [KDIM];   // Q_k = sum_e R_e*rw[e,k]        (phase B, atomic)
__device__ float g_c2b[KDIM];   // sum_e rw[e,k]^2                (phase B, atomic)
__device__ float g_P  [DDIM];   // sum_k pw[k,d]                  (phase C, atomic)
__device__ float g_T  [DDIM];   // sum_k Q_k*pw[k,d]              (phase C, atomic)
__device__ float g_U  [DDIM];   // sum_k c2b_k*pw[k,d]            (phase C, atomic)
__device__ float g_W  [DDIM];   // W_d = (P - (B/E)U) + ba*T      (phase D)
__device__ float g_ssq, g_SQ, g_Sbr;   // scalar accumulators (atomic)
__device__ float g_scf[2];      // C0, c1
__device__ int   g_cnt  [4];    // barrier counters (self-resetting)
__device__ int   g_sense[4];    // barrier sense (flips each use; replay-safe)

__device__ __forceinline__ float warp_sum(float v) {
    v += __shfl_xor_sync(~0u, v, 16);
    v += __shfl_xor_sync(~0u, v, 8);
    v += __shfl_xor_sync(~0u, v, 4);
    v += __shfl_xor_sync(~0u, v, 2);
    v += __shfl_xor_sync(~0u, v, 1);
    return v;
}

// sense-reversing grid barrier (all NBLK blocks resident by construction)
__device__ __forceinline__ void gridbar(int i) {
    __syncthreads();
    if (threadIdx.x == 0) {
        __threadfence();
        int s = g_sense[i];
        if (atomicAdd(&g_cnt[i], 1) == NBLK - 1) {
            g_cnt[i] = 0;
            __threadfence();
            atomicExch(&g_sense[i], s ^ 1);
        } else {
            while (atomicAdd(&g_sense[i], 0) == s) { __nanosleep(32); }
        }
        __threadfence();
    }
    __syncthreads();
}

__global__ __launch_bounds__(256, 4)
void kALL(const float* __restrict__ rw, const float* __restrict__ pw,
          const float* __restrict__ img, float* __restrict__ out)
{
    __shared__ float  sRed[8];
    __shared__ float  sQ[16], sC[16];
    __shared__ double dred[256];
    __shared__ float4 sW[256];
    __shared__ float  sBA, sS2;

    const int b    = blockIdx.x;
    const int t    = threadIdx.x;
    const int w    = t >> 5;
    const int lane = t & 31;

    // ================= phase A: R row sums (1 e-row/block) + zeroing =================
    {
        const int gt = b * 256 + t;
        if (gt < KDIM)              { g_Q[gt] = 0.f; g_c2b[gt] = 0.f; }
        else if (gt < KDIM + DDIM)  { int d = gt - KDIM; g_P[d] = 0.f; g_T[d] = 0.f; g_U[d] = 0.f; }
        else if (gt == KDIM + DDIM) { g_ssq = 0.f; g_SQ = 0.f; g_Sbr = 0.f; }

        const float4* row = (const float4*)(rw + (size_t)b * KDIM);
        float4 a = row[t];
        float4 c = row[t + 256];
        float s = a.x + a.y + a.z + a.w + c.x + c.y + c.z + c.w;
        s = warp_sum(s);
        if (lane == 0) sRed[w] = s;
        __syncthreads();
        if (t == 0) {
            float r = sRed[0] + sRed[1] + sRed[2] + sRed[3]
                    + sRed[4] + sRed[5] + sRed[6] + sRed[7];
            g_R[b] = r;
        }
    }
    gridbar(0);

    // ================= phase B: Q_k, c2b_k over rw (L2-hot), tile 8e x 256k ==========
    {
        const int kx = (b & 7) * 256;
        const int e0 = (b >> 3) * 8;
        if (t < 8) sRed[t] = g_R[e0 + t];
        __syncthreads();
        const int k = kx + t;
        float q = 0.f, c = 0.f;
        #pragma unroll
        for (int e = 0; e < 8; e++) {
            float x = rw[(size_t)(e0 + e) * KDIM + k];
            q += sRed[e] * x;
            c += x * x;
        }
        atomicAdd(&g_Q[k], q);
        atomicAdd(&g_c2b[k], c);
        float wq = warp_sum(q);
        float wc = warp_sum(c);
        if (lane == 0) { atomicAdd(&g_SQ, wq); atomicAdd(&g_Sbr, wc); }
    }
    gridbar(1);

    // ================= phase C: P,T,U,ssq over pw, tile 16k x 256d ===================
    {
        const int d  = (b & 3) * 256 + t;
        const int k0 = (b >> 2) * 16;
        if (t < 16) { sQ[t] = g_Q[k0 + t]; sC[t] = g_c2b[k0 + t]; }
        __syncthreads();
        float P = 0.f, T = 0.f, U = 0.f, S = 0.f;
        #pragma unroll
        for (int j = 0; j < 16; j++) {
            float x = pw[(size_t)(k0 + j) * DDIM + d];
            P += x;
            T += sQ[j] * x;
            U += sC[j] * x;
            S += x * x;
        }
        atomicAdd(&g_P[d], P);
        atomicAdd(&g_T[d], T);
        atomicAdd(&g_U[d], U);
        S = warp_sum(S);
        if (lane == 0) atomicAdd(&g_ssq, S);
    }
    gridbar(2);

    // ================= phase D: finalize (block 0 only) ==============================
    if (b == 0) {
        if (t == 0) {
            double Sa = (double)g_ssq / DDIM;
            double s1 = (double)KDIM - BETA * Sa;               // row-constant (var ~4e-11)
            double a  = 2.0 / (EDIM * s1);
            double s2 = (double)KDIM + BETA * (a * (double)g_SQ - (double)g_Sbr / EDIM);
            sBA = (float)(BETA * a);
            sS2 = (float)s2;
        }
        __syncthreads();
        const float ba = sBA;
        double ww = 0.0;
        #pragma unroll
        for (int r = 0; r < 4; r++) {
            int dd = t + 256 * r;
            float W = (g_P[dd] - (float)(BETA / EDIM) * g_U[dd]) + ba * g_T[dd];
            g_W[dd] = W;
            ww += (double)W * (double)W;
        }
        dred[t] = ww; __syncthreads();
        for (int st = 128; st > 0; st >>= 1) {
            if (t < st) dred[t] += dred[t + st];
            __syncthreads();
        }
        if (t == 0) {
            double s2 = (double)sS2;
            g_scf[0] = (float)((dred[0] / DDIM) / (s2 * s2));   // C0
            g_scf[1] = (float)(2.0 / (DDIM * s2));              // c1
        }
    }
    gridbar(3);

    // ================= phase E: per-row loss, 2 rows/warp, 16 rows/block =============
    {
        sW[t] = ((const float4*)g_W)[t];
        __syncthreads();
        const int r0 = b * 16 + w * 2;
        const int r1 = r0 + 1;
        const float4* x0 = (const float4*)(img + (size_t)r0 * DDIM);
        const float4* x1 = (const float4*)(img + (size_t)r1 * DDIM);

        float aW0 = 0.f, aI0 = 0.f, aW1 = 0.f, aI1 = 0.f;
        #pragma unroll
        for (int i = 0; i < 8; i++) {
            const int idx = lane + 32 * i;
            float4 xa = x0[idx];
            float4 xb = x1[idx];
            float4 W = sW[idx];
            aW0 += xa.x * W.x + xa.y * W.y + xa.z * W.z + xa.w * W.w;
            aI0 += xa.x * xa.x + xa.y * xa.y + xa.z * xa.z + xa.w * xa.w;
            aW1 += xb.x * W.x + xb.y * W.y + xb.z * W.z + xb.w * W.w;
            aI1 += xb.x * xb.x + xb.y * xb.y + xb.z * xb.z + xb.w * xb.w;
        }
        aW0 = warp_sum(aW0); aI0 = warp_sum(aI0);
        aW1 = warp_sum(aW1); aI1 = warp_sum(aI1);

        if (lane == 0) {
            const float C0 = g_scf[0], c1 = g_scf[1];
            out[r0] = C0 - c1 * aW0 + aI0 * (1.0f / DDIM);
            out[r1] = C0 - c1 * aW1 + aI1 * (1.0f / DDIM);
        }
    }
}

// ---------------- launch ----------------
extern "C" void kernel_launch(void* const* d_in, const int* in_sizes, int n_in,
                              void* d_out, int out_size)
{
    const float* images    = (const float*)d_in[0];
    const float* project_w = (const float*)d_in[1];
    const float* rec_w     = (const float*)d_in[2];
    float* out = (float*)d_out;

    kALL<<<NBLK, 256>>>(rec_w, project_w, images, out);
}

// round 15
// speedup vs baseline: 1.5000x; 1.5000x over previous
#include <cuda_runtime.h>
#include <cstdint>

#define BATCH 8192
#define DDIM  1024
#define KDIM  2048
#define EDIM  512
#define BETA  0.001
#define BETAF 0.001f

// ---------------- scratch (static device arrays; no cudaMalloc) ----------------
__device__ float g_R  [EDIM];   // R_e = sum_k rw[e,k]            (kA, no atomics)
__device__ float g_Q  [KDIM];   // Q_k = sum_e R_e*rw[e,k]        (kB, atomic)
__device__ float g_c2b[KDIM];   // sum_e rw[e,k]^2                (kB, atomic)
__device__ float g_P  [DDIM];   // sum_k pw[k,d]                  (kC, atomic)
__device__ float g_T  [DDIM];   // sum_k Q_k*pw[k,d]              (kC, atomic)
__device__ float g_U  [DDIM];   // sum_k c2b_k*pw[k,d]            (kC, atomic)
__device__ float g_W  [DDIM];   // W_d = (P - (B/E)U) + ba*T
__device__ float g_ssq, g_SQ, g_Sbr;   // scalar accumulators (atomic)
__device__ float g_scf[2];      // C0, c1
__device__ int   g_cnt;         // kC last-block counter (self-reset)

__device__ __forceinline__ float warp_sum(float v) {
    v += __shfl_xor_sync(~0u, v, 16);
    v += __shfl_xor_sync(~0u, v, 8);
    v += __shfl_xor_sync(~0u, v, 4);
    v += __shfl_xor_sync(~0u, v, 2);
    v += __shfl_xor_sync(~0u, v, 1);
    return v;
}

// ---------------- kA: R row sums (1 e-row/block, no atomics) + zeroing ----------------
__global__ __launch_bounds__(256)
void kA(const float* __restrict__ rw) {
    __shared__ float sRed[8];
    const int b    = blockIdx.x;           // 0..511 == e row
    const int t    = threadIdx.x;
    const int w    = t >> 5;
    const int lane = t & 31;

    const int gt = b * 256 + t;
    if (gt < KDIM)              { g_Q[gt] = 0.f; g_c2b[gt] = 0.f; }
    else if (gt < KDIM + DDIM)  { int d = gt - KDIM; g_P[d] = 0.f; g_T[d] = 0.f; g_U[d] = 0.f; }
    else if (gt == KDIM + DDIM) { g_ssq = 0.f; g_SQ = 0.f; g_Sbr = 0.f; g_cnt = 0; }

    const float4* row = (const float4*)(rw + (size_t)b * KDIM);
    float4 a = row[t];
    float4 c = row[t + 256];
    float s = a.x + a.y + a.z + a.w + c.x + c.y + c.z + c.w;
    s = warp_sum(s);
    if (lane == 0) sRed[w] = s;
    __syncthreads();
    if (t == 0)
        g_R[b] = sRed[0] + sRed[1] + sRed[2] + sRed[3]
               + sRed[4] + sRed[5] + sRed[6] + sRed[7];
}

// ---------------- kB: Q_k, c2b_k over rw (L2-hot after kA), tile 16e x 256k -----------
__global__ __launch_bounds__(256)
void kB(const float* __restrict__ rw) {
    __shared__ float sR[16];
    const int t  = threadIdx.x;
    const int kx = (blockIdx.x & 7) * 256;     // 8 x-chunks
    const int e0 = (blockIdx.x >> 3) * 16;     // 32 e-chunks -> 256 blocks
    if (t < 16) sR[t] = g_R[e0 + t];
    __syncthreads();

    const int k = kx + t;
    float q = 0.f, c = 0.f;
    #pragma unroll
    for (int e = 0; e < 16; e++) {
        float x = rw[(size_t)(e0 + e) * KDIM + k];
        q += sR[e] * x;
        c += x * x;
    }
    atomicAdd(&g_Q[k], q);
    atomicAdd(&g_c2b[k], c);
    float wq = warp_sum(q);
    float wc = warp_sum(c);
    if ((t & 31) == 0) { atomicAdd(&g_SQ, wq); atomicAdd(&g_Sbr, wc); }
}

// ---------------- kC: P,T,U,ssq over pw (16k x 256d tiles) + last-block finalize ------
__global__ __launch_bounds__(256)
void kC(const float* __restrict__ pw) {
    __shared__ float sQ[16], sC[16];
    const int t  = threadIdx.x;
    const int d  = (blockIdx.x & 3) * 256 + t;   // 4 x-chunks
    const int k0 = (blockIdx.x >> 2) * 16;       // 128 k-chunks -> 512 blocks
    if (t < 16) { sQ[t] = g_Q[k0 + t]; sC[t] = g_c2b[k0 + t]; }
    __syncthreads();

    float P = 0.f, T = 0.f, U = 0.f, S = 0.f;
    #pragma unroll
    for (int j = 0; j < 16; j++) {
        float x = __ldcs(&pw[(size_t)(k0 + j) * DDIM + d]);
        P += x;
        T += sQ[j] * x;
        U += sC[j] * x;
        S += x * x;
    }
    atomicAdd(&g_P[d], P);
    atomicAdd(&g_T[d], T);
    atomicAdd(&g_U[d], U);
    S = warp_sum(S);
    if ((t & 31) == 0) atomicAdd(&g_ssq, S);

    __threadfence();
    __shared__ int isLast;
    if (t == 0)
        isLast = (atomicAdd(&g_cnt, 1) == (int)gridDim.x - 1);
    __syncthreads();
    if (!isLast) return;

    // ---- finalization (single block) ----
    __shared__ double dred[256];
    __shared__ float sBA, sS2;
    if (t == 0) {
        double Sa = (double)g_ssq / DDIM;
        double s1 = (double)KDIM - BETA * Sa;            // row-constant (var ~4e-11 rel)
        double a  = 2.0 / (EDIM * s1);
        double s2 = (double)KDIM + BETA * (a * (double)g_SQ - (double)g_Sbr / EDIM);
        sBA = (float)(BETA * a);
        sS2 = (float)s2;
        g_cnt = 0;                                       // self-clean for graph replay
    }
    __syncthreads();
    const float ba = sBA;
    double ww = 0.0;
    #pragma unroll
    for (int r = 0; r < 4; r++) {
        int dd = t + 256 * r;
        float W = (g_P[dd] - (float)(BETA / EDIM) * g_U[dd]) + ba * g_T[dd];
        g_W[dd] = W;
        ww += (double)W * (double)W;
    }
    dred[t] = ww; __syncthreads();
    for (int st = 128; st > 0; st >>= 1) {
        if (t < st) dred[t] += dred[t + st];
        __syncthreads();
    }
    if (t == 0) {
        double s2 = (double)sS2;
        g_scf[0] = (float)((dred[0] / DDIM) / (s2 * s2));   // C0
        g_scf[1] = (float)(2.0 / (DDIM * s2));              // c1
    }
}

// ---------------- kD: loss_i = C0 - c1*dot(x,W) + dot(x,x)/D  (2 rows/warp) ----------
__global__ __launch_bounds__(128)
void kD(const float* __restrict__ img, float* __restrict__ out) {
    __shared__ float4 sW[256];
    const int t    = threadIdx.x;          // 0..127
    const int w    = t >> 5;               // 0..3
    const int lane = t & 31;
    const int r0   = blockIdx.x * 8 + w * 2;
    const int r1   = r0 + 1;

    sW[t] = ((const float4*)g_W)[t];
    sW[t + 128] = ((const float4*)g_W)[t + 128];
    __syncthreads();

    const float4* x0 = (const float4*)(img + (size_t)r0 * DDIM);
    const float4* x1 = (const float4*)(img + (size_t)r1 * DDIM);

    float aW0 = 0.f, aI0 = 0.f, aW1 = 0.f, aI1 = 0.f;
    #pragma unroll
    for (int i = 0; i < 8; i++) {
        const int idx = lane + 32 * i;
        float4 xa = __ldcs(&x0[idx]);
        float4 xb = __ldcs(&x1[idx]);
        float4 W = sW[idx];
        aW0 += xa.x * W.x + xa.y * W.y + xa.z * W.z + xa.w * W.w;
        aI0 += xa.x * xa.x + xa.y * xa.y + xa.z * xa.z + xa.w * xa.w;
        aW1 += xb.x * W.x + xb.y * W.y + xb.z * W.z + xb.w * W.w;
        aI1 += xb.x * xb.x + xb.y * xb.y + xb.z * xb.z + xb.w * xb.w;
    }
    aW0 = warp_sum(aW0); aI0 = warp_sum(aI0);
    aW1 = warp_sum(aW1); aI1 = warp_sum(aI1);

    if (lane == 0) {
        const float C0 = g_scf[0], c1 = g_scf[1];
        out[r0] = C0 - c1 * aW0 + aI0 * (1.0f / DDIM);
        out[r1] = C0 - c1 * aW1 + aI1 * (1.0f / DDIM);
    }
}

// ---------------- launch ----------------
extern "C" void kernel_launch(void* const* d_in, const int* in_sizes, int n_in,
                              void* d_out, int out_size)
{
    const float* images    = (const float*)d_in[0];
    const float* project_w = (const float*)d_in[1];
    const float* rec_w     = (const float*)d_in[2];
    float* out = (float*)d_out;

    kA<<<EDIM, 256>>>(rec_w);             // 512 blocks: zero + R (rw -> L2)
    kB<<<256, 256>>>(rec_w);              // 256 blocks: Q, c2b, SQ, Sbr (L2-hot)
    kC<<<512, 256>>>(project_w);          // 512 blocks: P,T,U,ssq + W,C0,c1
    kD<<<BATCH / 8, 128>>>(images, out);  // 1024 blocks: per-row loss
}